// round 8
// baseline (speedup 1.0000x reference)
#include <cuda_runtime.h>
#include <cuda_bf16.h>
#include <cstdint>

// out = X @ W_eff^T + bias, W_eff = W + 2*B@A
// Single-pass TF32 GEMM via mma.sync.m16n8k8 (base sm_103 target).
// R6: warp tile 32x64 (A-cvt amortized over 2x MMAs), BK=32, 3-stage,
// 256 thr/CTA, 2 CTAs/SM. W pre-rounded tf32; A rounded cvt.rna in regs.

#define M_TOTAL 16384
#define N_DIM   1024
#define K_DIM   1024
#define R_RANK  16

#define BM 128
#define BN 128
#define BK 32
#define NCHUNK (K_DIM / BK)   // 32
#define KSTEPS (BK / 8)       // 4

// stage: X fp32 128x32 (16KB, 128B rows) + W tf32 128x32 (16KB)
#define STG_X 0
#define STG_W 16384
#define STAGE_BYTES 32768
#define NSTAGE 3
#define SMEM_BYTES (NSTAGE * STAGE_BYTES)   // 96KB -> 2 CTAs/SM

__device__ float g_Wtf[N_DIM * K_DIM];   // W_eff, tf32-rounded fp32 bits

// ---------------- PTX helpers ----------------
__device__ __forceinline__ uint32_t smem_u32(const void* p) {
    uint32_t a;
    asm("{ .reg .u64 t; cvta.to.shared.u64 t, %1; cvt.u32.u64 %0, t; }" : "=r"(a) : "l"(p));
    return a;
}

#define CP_ASYNC16(dst, src) \
    asm volatile("cp.async.cg.shared.global [%0], [%1], 16;" :: "r"(dst), "l"(src))
#define CP_COMMIT() asm volatile("cp.async.commit_group;" ::: "memory")
#define CP_WAIT1()  asm volatile("cp.async.wait_group 1;" ::: "memory")
#define CP_WAIT0()  asm volatile("cp.async.wait_group 0;" ::: "memory")

#define LDSM_X4(r0, r1, r2, r3, addr) \
    asm volatile("ldmatrix.sync.aligned.m8n8.x4.shared.b16 {%0,%1,%2,%3}, [%4];" \
                 : "=r"(r0), "=r"(r1), "=r"(r2), "=r"(r3) : "r"(addr))

#define MMA_TF32(d, a0, a1, a2, a3, b0, b1) \
    asm volatile("mma.sync.aligned.m16n8k8.row.col.f32.tf32.tf32.f32 " \
                 "{%0,%1,%2,%3}, {%4,%5,%6,%7}, {%8,%9}, {%0,%1,%2,%3};" \
                 : "+f"((d)[0]), "+f"((d)[1]), "+f"((d)[2]), "+f"((d)[3]) \
                 : "r"(a0), "r"(a1), "r"(a2), "r"(a3), "r"(b0), "r"(b1))

__device__ __forceinline__ uint32_t cvt_tf32(uint32_t x) {
    uint32_t r;
    asm("cvt.rna.tf32.f32 %0, %1;" : "=r"(r) : "r"(x));
    return r;
}

// ---------------------------------------------------------------------------
// Prep: W_eff = W + 2*B@A, rounded to tf32.
// ---------------------------------------------------------------------------
__global__ void build_weff_tf32_kernel(const float* __restrict__ W,
                                       const float* __restrict__ A,
                                       const float* __restrict__ Bm) {
    const int o = blockIdx.x;
    const int t = threadIdx.x;
    __shared__ float brow[R_RANK];
    if (t < R_RANK) brow[t] = 2.0f * Bm[o * R_RANK + t];
    __syncthreads();

    for (int k4 = t * 4; k4 < K_DIM; k4 += blockDim.x * 4) {
        float4 w = *(const float4*)&W[o * K_DIM + k4];
        float v[4] = {w.x, w.y, w.z, w.w};
        #pragma unroll
        for (int r = 0; r < R_RANK; r++) {
            float br = brow[r];
            const float4 a = *(const float4*)&A[r * K_DIM + k4];
            v[0] = fmaf(br, a.x, v[0]); v[1] = fmaf(br, a.y, v[1]);
            v[2] = fmaf(br, a.z, v[2]); v[3] = fmaf(br, a.w, v[3]);
        }
        uint4 o4;
        o4.x = cvt_tf32(__float_as_uint(v[0]));
        o4.y = cvt_tf32(__float_as_uint(v[1]));
        o4.z = cvt_tf32(__float_as_uint(v[2]));
        o4.w = cvt_tf32(__float_as_uint(v[3]));
        *(uint4*)&g_Wtf[o * K_DIM + k4] = o4;
    }
}

// ---------------------------------------------------------------------------
// Main GEMM: 128x128 CTA, 256 threads (8 warps, 4M x 2N), warp tile 32x64.
// ---------------------------------------------------------------------------
__global__ __launch_bounds__(256, 2) void lora_gemm_tf32_kernel(
    const float* __restrict__ X,
    const float* __restrict__ bias,
    float* __restrict__ Out) {
    extern __shared__ char smem[];
    const uint32_t sbase = smem_u32(smem);
    const int tid = threadIdx.x;
    const int lane = tid & 31;
    const int wid = tid >> 5;          // 0..7
    const int wm = wid & 3;            // 4 warps along M (32 rows)
    const int wn = wid >> 2;           // 2 warps along N (64 cols)

    const int block_m = blockIdx.y * BM;
    const int block_n = blockIdx.x * BN;

    // ---- cp.async: 8 x 16B per thread per stage (X 1024 + W 1024 chunks).
    // i-th chunk: row advances 32 per i -> constant strides, 2 base ptrs only.
    const int cr = tid >> 3;           // 0..31 base row
    const int c8 = tid & 7;            // 16B chunk in 128B row
    const uint32_t dst_off = (uint32_t)(cr * 128 + ((c8 ^ (cr & 7)) << 4));
    const char* xsrc = (const char*)(X + (size_t)(block_m + cr) * K_DIM + c8 * 4);
    const char* wsrc = (const char*)(g_Wtf + (size_t)(block_n + cr) * K_DIM + c8 * 4);
    // i-step: +32 rows -> dst +4096B (swizzle invariant: (cr+32)&7 == cr&7), src +32*4096B

    // ---- ldmatrix components ----
    const int arow_l = (lane & 7) + ((lane >> 3) & 1) * 8;  // row in 16-blk
    const int khalf  = (lane >> 4) & 1;                      // 16B chunk +0/+1

    float acc[2][8][4];
    #pragma unroll
    for (int mf = 0; mf < 2; mf++)
        #pragma unroll
        for (int nf = 0; nf < 8; nf++)
            #pragma unroll
            for (int r = 0; r < 4; r++)
                acc[mf][nf][r] = 0.0f;

    // prologue: stages 0, 1
    #pragma unroll
    for (int s = 0; s < 2; s++) {
        const uint32_t sb = sbase + s * STAGE_BYTES;
        #pragma unroll
        for (int i = 0; i < 4; i++) {
            CP_ASYNC16(sb + STG_X + dst_off + i * 4096, xsrc + s * (BK * 4) + i * (32 * K_DIM * 4));
            CP_ASYNC16(sb + STG_W + dst_off + i * 4096, wsrc + s * (BK * 4) + i * (32 * K_DIM * 4));
        }
        CP_COMMIT();
    }

    #pragma unroll 1
    for (int c = 0; c < NCHUNK; c++) {
        if (c + 1 < NCHUNK) CP_WAIT1(); else CP_WAIT0();
        __syncthreads();

        if (c + 2 < NCHUNK) {
            const uint32_t sb = sbase + (uint32_t)(((c + 2) % NSTAGE) * STAGE_BYTES);
            const int ko = (c + 2) * (BK * 4);
            #pragma unroll
            for (int i = 0; i < 4; i++) {
                CP_ASYNC16(sb + STG_X + dst_off + i * 4096, xsrc + ko + i * (32 * K_DIM * 4));
                CP_ASYNC16(sb + STG_W + dst_off + i * 4096, wsrc + ko + i * (32 * K_DIM * 4));
            }
            CP_COMMIT();
        }

        const uint32_t buf = sbase + (uint32_t)((c % NSTAGE) * STAGE_BYTES);

        #pragma unroll
        for (int ks = 0; ks < KSTEPS; ks++) {
            const int kchunk = ks * 2 + khalf;   // 0..7
            uint32_t a[2][4], b[4][4];
            // A: 2 m-halves of the 32-row warp tile, cvt.rna in regs
            #pragma unroll
            for (int mf = 0; mf < 2; mf++) {
                const int row = wm * 32 + mf * 16 + arow_l;
                const uint32_t ao = buf + STG_X +
                    (uint32_t)(row * 128 + ((kchunk ^ (row & 7)) << 4));
                LDSM_X4(a[mf][0], a[mf][1], a[mf][2], a[mf][3], ao);
                a[mf][0] = cvt_tf32(a[mf][0]);
                a[mf][1] = cvt_tf32(a[mf][1]);
                a[mf][2] = cvt_tf32(a[mf][2]);
                a[mf][3] = cvt_tf32(a[mf][3]);
            }
            // B: 4 n16-blocks of the 64-col warp tile (pre-rounded, no cvt)
            #pragma unroll
            for (int np = 0; np < 4; np++) {
                const int row = wn * 64 + np * 16 + arow_l;
                const uint32_t bo = buf + STG_W +
                    (uint32_t)(row * 128 + ((kchunk ^ (row & 7)) << 4));
                LDSM_X4(b[np][0], b[np][1], b[np][2], b[np][3], bo);
            }
            #pragma unroll
            for (int mf = 0; mf < 2; mf++)
                #pragma unroll
                for (int nf = 0; nf < 8; nf++) {
                    const int np = nf >> 1, h = nf & 1;
                    MMA_TF32(acc[mf][nf], a[mf][0], a[mf][1], a[mf][2], a[mf][3],
                             b[np][h], b[np][h + 2]);
                }
        }
        // buffer reuse ordered by next iteration's wait + syncthreads
    }

    // ---- epilogue: bias + direct stores ----
    const int mrow = block_m + wm * 32 + (lane >> 2);
    const int ncol = block_n + wn * 64 + 2 * (lane & 3);
    #pragma unroll
    for (int mf = 0; mf < 2; mf++) {
        #pragma unroll
        for (int nf = 0; nf < 8; nf++) {
            const int n = ncol + nf * 8;
            const float2 bv = *(const float2*)&bias[n];
            const int r0 = mrow + mf * 16;
            float2 o0 = make_float2(acc[mf][nf][0] + bv.x, acc[mf][nf][1] + bv.y);
            float2 o1 = make_float2(acc[mf][nf][2] + bv.x, acc[mf][nf][3] + bv.y);
            *(float2*)&Out[(size_t)r0 * N_DIM + n] = o0;
            *(float2*)&Out[(size_t)(r0 + 8) * N_DIM + n] = o1;
        }
    }
}

// ---------------------------------------------------------------------------
extern "C" void kernel_launch(void* const* d_in, const int* in_sizes, int n_in,
                              void* d_out, int out_size) {
    const float* x  = (const float*)d_in[0];
    const float* W  = (const float*)d_in[1];
    const float* b  = (const float*)d_in[2];
    const float* A  = (const float*)d_in[3];
    const float* Bm = (const float*)d_in[4];
    float* out = (float*)d_out;

    cudaFuncSetAttribute(lora_gemm_tf32_kernel,
                         cudaFuncAttributeMaxDynamicSharedMemorySize, SMEM_BYTES);

    build_weff_tf32_kernel<<<N_DIM, 256>>>(W, A, Bm);

    dim3 grid(N_DIM / BN, M_TOTAL / BM);   // (8, 128)
    lora_gemm_tf32_kernel<<<grid, 256, SMEM_BYTES>>>(x, b, out);
}

// round 9
// speedup vs baseline: 1.3435x; 1.3435x over previous
#include <cuda_runtime.h>
#include <cuda_bf16.h>
#include <cstdint>

// out = X @ W_eff^T + bias, W_eff = W + 2*B@A
// Single-pass TF32 GEMM via mma.sync.m16n8k8 (base sm_103 target).
// R9: R5 skeleton (BK=64, 512 thr, 3x64KB stages) + warp tile 16x64 (8Mx2N)
// + NO cvt on A (HW RZ-truncates fp32->tf32); the truncation's systematic
// -3.52e-4 scaling is cancelled by folding (1+3.52e-4) into W_eff pre-round.

#define M_TOTAL 16384
#define N_DIM   1024
#define K_DIM   1024
#define R_RANK  16

#define BM 128
#define BN 128
#define BK 64
#define NCHUNK (K_DIM / BK)   // 16
#define KSTEPS (BK / 8)       // 8

// E[relative truncation loss] for fp32->tf32 RZ on log-uniform mantissas:
// 2^-11 * E[1/m] = 2^-11 * 0.7213
#define TRUNC_COMP 1.000352f

// stage layout: X fp32 128x64 (32KB) + W tf32 128x64 (32KB)
#define STG_X 0
#define STG_W 32768
#define STAGE_BYTES 65536
#define NSTAGE 3
#define SMEM_BYTES (NSTAGE * STAGE_BYTES)   // 192KB

__device__ float g_Wtf[N_DIM * K_DIM];   // W_eff, compensated + tf32-rounded

// ---------------- PTX helpers ----------------
__device__ __forceinline__ uint32_t smem_u32(const void* p) {
    uint32_t a;
    asm("{ .reg .u64 t; cvta.to.shared.u64 t, %1; cvt.u32.u64 %0, t; }" : "=r"(a) : "l"(p));
    return a;
}

#define CP_ASYNC16(dst, src) \
    asm volatile("cp.async.cg.shared.global [%0], [%1], 16;" :: "r"(dst), "l"(src))
#define CP_COMMIT() asm volatile("cp.async.commit_group;" ::: "memory")
#define CP_WAIT1()  asm volatile("cp.async.wait_group 1;" ::: "memory")
#define CP_WAIT0()  asm volatile("cp.async.wait_group 0;" ::: "memory")

#define LDSM_X4(r0, r1, r2, r3, addr) \
    asm volatile("ldmatrix.sync.aligned.m8n8.x4.shared.b16 {%0,%1,%2,%3}, [%4];" \
                 : "=r"(r0), "=r"(r1), "=r"(r2), "=r"(r3) : "r"(addr))

#define MMA_TF32(d, a0, a1, a2, a3, b0, b1) \
    asm volatile("mma.sync.aligned.m16n8k8.row.col.f32.tf32.tf32.f32 " \
                 "{%0,%1,%2,%3}, {%4,%5,%6,%7}, {%8,%9}, {%0,%1,%2,%3};" \
                 : "+f"((d)[0]), "+f"((d)[1]), "+f"((d)[2]), "+f"((d)[3]) \
                 : "r"(a0), "r"(a1), "r"(a2), "r"(a3), "r"(b0), "r"(b1))

__device__ __forceinline__ uint32_t cvt_tf32(uint32_t x) {
    uint32_t r;
    asm("cvt.rna.tf32.f32 %0, %1;" : "=r"(r) : "r"(x));
    return r;
}

// ---------------------------------------------------------------------------
// Prep: W_eff = (W + 2*B@A) * TRUNC_COMP, rounded to tf32 (rna).
// ---------------------------------------------------------------------------
__global__ void build_weff_tf32_kernel(const float* __restrict__ W,
                                       const float* __restrict__ A,
                                       const float* __restrict__ Bm) {
    const int o = blockIdx.x;
    const int t = threadIdx.x;
    __shared__ float brow[R_RANK];
    if (t < R_RANK) brow[t] = 2.0f * Bm[o * R_RANK + t];
    __syncthreads();

    for (int k4 = t * 4; k4 < K_DIM; k4 += blockDim.x * 4) {
        float4 w = *(const float4*)&W[o * K_DIM + k4];
        float v[4] = {w.x, w.y, w.z, w.w};
        #pragma unroll
        for (int r = 0; r < R_RANK; r++) {
            float br = brow[r];
            const float4 a = *(const float4*)&A[r * K_DIM + k4];
            v[0] = fmaf(br, a.x, v[0]); v[1] = fmaf(br, a.y, v[1]);
            v[2] = fmaf(br, a.z, v[2]); v[3] = fmaf(br, a.w, v[3]);
        }
        uint4 o4;
        o4.x = cvt_tf32(__float_as_uint(v[0] * TRUNC_COMP));
        o4.y = cvt_tf32(__float_as_uint(v[1] * TRUNC_COMP));
        o4.z = cvt_tf32(__float_as_uint(v[2] * TRUNC_COMP));
        o4.w = cvt_tf32(__float_as_uint(v[3] * TRUNC_COMP));
        *(uint4*)&g_Wtf[o * K_DIM + k4] = o4;
    }
}

// ---------------------------------------------------------------------------
// Main GEMM: 128x128 CTA, 512 threads (16 warps: 8M x 2N), warp tile 16x64.
// ---------------------------------------------------------------------------
__global__ __launch_bounds__(512) void lora_gemm_tf32_kernel(
    const float* __restrict__ X,
    const float* __restrict__ bias,
    float* __restrict__ Out) {
    extern __shared__ char smem[];
    const uint32_t sbase = smem_u32(smem);
    const int tid = threadIdx.x;
    const int lane = tid & 31;
    const int wid = tid >> 5;          // 0..15
    const int wm = wid & 7;            // 8 warps along M (16 rows each)
    const int wn = wid >> 3;           // 2 warps along N (64 cols each)

    const int block_m = blockIdx.y * BM;
    const int block_n = blockIdx.x * BN;

    // ---- cp.async plan: 8 x 16B chunks/thread/stage (X 2048 + W 2048) ----
    uint32_t cp_dst[8];
    const char* cp_src[8];
    #pragma unroll
    for (int i = 0; i < 8; i++) {
        int idx = tid + (i & 3) * 512;     // 0..2047
        int r = idx >> 4, c16 = idx & 15;  // row 0..127, 16B chunk 0..15
        uint32_t off = (uint32_t)(r * 256 + ((c16 ^ (r & 15)) << 4));
        if (i < 4) {
            cp_dst[i] = sbase + STG_X + off;
            cp_src[i] = (const char*)(X + (size_t)(block_m + r) * K_DIM + c16 * 4);
        } else {
            cp_dst[i] = sbase + STG_W + off;
            cp_src[i] = (const char*)(g_Wtf + (size_t)(block_n + r) * K_DIM + c16 * 4);
        }
    }

    // ---- ldmatrix row/swizzle components ----
    const int arow_l = (lane & 7) + ((lane >> 3) & 1) * 8;  // row in 16-blk
    const int khalf  = (lane >> 4) & 1;                      // 16B chunk +0/+1

    const int a_row = wm * 16 + arow_l;                      // A row, fixed
    const uint32_t a_base = (uint32_t)(a_row * 256);
    const int a_sw = a_row & 15;

    float acc[8][4];
    #pragma unroll
    for (int nf = 0; nf < 8; nf++)
        #pragma unroll
        for (int r = 0; r < 4; r++)
            acc[nf][r] = 0.0f;

    // prologue: stages 0, 1
    #pragma unroll
    for (int i = 0; i < 8; i++) CP_ASYNC16(cp_dst[i], cp_src[i]);
    CP_COMMIT();
    #pragma unroll
    for (int i = 0; i < 8; i++) CP_ASYNC16(cp_dst[i] + STAGE_BYTES, cp_src[i] + BK * 4);
    CP_COMMIT();

    for (int c = 0; c < NCHUNK; c++) {
        if (c + 1 < NCHUNK) CP_WAIT1(); else CP_WAIT0();
        __syncthreads();

        if (c + 2 < NCHUNK) {
            const uint32_t stg = (uint32_t)(((c + 2) % NSTAGE) * STAGE_BYTES);
            #pragma unroll
            for (int i = 0; i < 8; i++)
                CP_ASYNC16(cp_dst[i] + stg, cp_src[i] + (c + 2) * BK * 4);
            CP_COMMIT();
        }

        const uint32_t buf = sbase + (uint32_t)((c % NSTAGE) * STAGE_BYTES);

        #pragma unroll
        for (int ks = 0; ks < KSTEPS; ks++) {
            const int kchunk = ks * 2 + khalf;
            uint32_t a[4], b[4][4];
            // A fragment: one m16 block, raw fp32 bits (HW truncates to tf32)
            LDSM_X4(a[0], a[1], a[2], a[3],
                    buf + STG_X + a_base + (uint32_t)((kchunk ^ a_sw) << 4));
            // B fragments: 4 n16-blocks of the 64-col warp tile
            // regs: r0=(n+0,k0-3) r1=(n+8,k0-3) r2=(n+0,k4-7) r3=(n+8,k4-7)
            #pragma unroll
            for (int np = 0; np < 4; np++) {
                const int row = wn * 64 + np * 16 + arow_l;
                const uint32_t bo = buf + STG_W +
                    (uint32_t)(row * 256 + ((kchunk ^ (row & 15)) << 4));
                LDSM_X4(b[np][0], b[np][1], b[np][2], b[np][3], bo);
            }
            #pragma unroll
            for (int nf = 0; nf < 8; nf++) {
                const int np = nf >> 1, h = nf & 1;
                MMA_TF32(acc[nf], a[0], a[1], a[2], a[3], b[np][h], b[np][h + 2]);
            }
        }
        // buffer reuse ordered by next iteration's wait + syncthreads
    }

    // ---- epilogue: bias + direct stores ----
    const int mrow = block_m + wm * 16 + (lane >> 2);
    const int ncol = block_n + wn * 64 + 2 * (lane & 3);
    #pragma unroll
    for (int nf = 0; nf < 8; nf++) {
        const int n = ncol + nf * 8;
        const float2 bv = *(const float2*)&bias[n];
        float2 o0 = make_float2(acc[nf][0] + bv.x, acc[nf][1] + bv.y);
        float2 o1 = make_float2(acc[nf][2] + bv.x, acc[nf][3] + bv.y);
        *(float2*)&Out[(size_t)mrow * N_DIM + n] = o0;
        *(float2*)&Out[(size_t)(mrow + 8) * N_DIM + n] = o1;
    }
}

// ---------------------------------------------------------------------------
extern "C" void kernel_launch(void* const* d_in, const int* in_sizes, int n_in,
                              void* d_out, int out_size) {
    const float* x  = (const float*)d_in[0];
    const float* W  = (const float*)d_in[1];
    const float* b  = (const float*)d_in[2];
    const float* A  = (const float*)d_in[3];
    const float* Bm = (const float*)d_in[4];
    float* out = (float*)d_out;

    cudaFuncSetAttribute(lora_gemm_tf32_kernel,
                         cudaFuncAttributeMaxDynamicSharedMemorySize, SMEM_BYTES);

    build_weff_tf32_kernel<<<N_DIM, 256>>>(W, A, Bm);

    dim3 grid(N_DIM / BN, M_TOTAL / BM);   // (8, 128)
    lora_gemm_tf32_kernel<<<grid, 512, SMEM_BYTES>>>(x, b, out);
}